// round 7
// baseline (speedup 1.0000x reference)
#include <cuda_runtime.h>
#include <cuda_bf16.h>

// Problem constants (fixed by reference setup_inputs)
#define N_B      32
#define N_C      3
#define HW       4096      // 64*64
#define HW4      1024      // HW / 4
#define N_EMBD   896
#define INNER    128       // 896 / 7
#define N_LVL    7
#define N_CLS    1000
#define ROOT_OFF 768       // 6 * INNER

#define NBLK     40        // 32 mean blocks + 8 classifier blocks
#define NTHR     512
#define KCHUNK   125       // k per classifier block (8 * 125 = 1000)
#define NCLS_BLK 8

// Scratch (__device__ globals; allocations forbidden). Counters are monotonic
// (never reset) => generation = count/N is the launch index, valid on the
// correctness call and every graph replay (launches are stream-ordered).
__device__ float4 g_coef[N_B];              // {c0, c1, c2, tag_bits}
__device__ unsigned long long g_mean_ctr;   // +32 per launch (gen source only)
__device__ unsigned long long g_cls_ctr;    // +8  per launch (gen source only)

// ---------------------------------------------------------------------------
// One kernel. Tagged-data sync: the readiness flag travels IN the 16B coef
// line, so consumers need no counter round, no fences, no post-wait barriers.
//  blocks 0..31  (mean): gen atomic (overlaps x loads), channel means,
//                        ONE stcg of {c0,c1,c2,gen+1}, EXIT.
//  blocks 32..39 (cls):  gen atomic (overlaps cls_w loads), hoisted loads,
//                        collapse to sP={A+cls_b,W0,W1,W2} in shared; then
//                        each WARP polls its own 2 batches' tagged lines and
//                        writes its 2x125 outputs immediately.
// ---------------------------------------------------------------------------
__global__ __launch_bounds__(NTHR) void k_all(
    const float* __restrict__ x,
    const float* __restrict__ emb_w,
    const float* __restrict__ emb_b,
    const float* __restrict__ cls_w,
    const float* __restrict__ cls_b,
    float* __restrict__ out)
{
    const int tid  = threadIdx.x;
    const int blk  = blockIdx.x;
    const int lane = tid & 31;

    if (blk < N_B) {
        // ======================= mean (publisher) blocks ====================
        unsigned int tag = 0;
        if (tid == 0) {
            // Launch generation; latency overlaps the x loads below.
            unsigned long long my = atomicAdd(&g_mean_ctr, 1ULL);
            tag = (unsigned int)(my / N_B) + 1u;
        }
        const float4* xb = (const float4*)(x + (size_t)blk * (N_C * HW));
        float s0, s1, s2;
        {
            float4 a0 = xb[0 * HW4 + tid], a1 = xb[0 * HW4 + 512 + tid];
            float4 b0 = xb[1 * HW4 + tid], b1 = xb[1 * HW4 + 512 + tid];
            float4 c0 = xb[2 * HW4 + tid], c1 = xb[2 * HW4 + 512 + tid];
            s0 = (a0.x + a0.y + a0.z + a0.w) + (a1.x + a1.y + a1.z + a1.w);
            s1 = (b0.x + b0.y + b0.z + b0.w) + (b1.x + b1.y + b1.z + b1.w);
            s2 = (c0.x + c0.y + c0.z + c0.w) + (c1.x + c1.y + c1.z + c1.w);
        }
        #pragma unroll
        for (int off = 16; off > 0; off >>= 1) {
            s0 += __shfl_xor_sync(0xFFFFFFFFu, s0, off);
            s1 += __shfl_xor_sync(0xFFFFFFFFu, s1, off);
            s2 += __shfl_xor_sync(0xFFFFFFFFu, s2, off);
        }
        __shared__ float wr[16][3];
        const int wid = tid >> 5;
        if (lane == 0) { wr[wid][0] = s0; wr[wid][1] = s1; wr[wid][2] = s2; }
        __syncthreads();
        if (tid < 16) {
            float a0 = wr[tid][0], a1 = wr[tid][1], a2 = wr[tid][2];
            #pragma unroll
            for (int off = 8; off > 0; off >>= 1) {
                a0 += __shfl_xor_sync(0xFFFFu, a0, off);
                a1 += __shfl_xor_sync(0xFFFFu, a1, off);
                a2 += __shfl_xor_sync(0xFFFFu, a2, off);
            }
            if (tid == 0) {
                // Data + readiness tag in ONE 16B L2 store (single sector).
                float4 cf = make_float4(a0 * (1.0f / HW), a1 * (1.0f / HW),
                                        a2 * (1.0f / HW), __uint_as_float(tag));
                __stcg(&g_coef[blk], cf);
            }
        }
        return;                                        // publishers exit
    }

    // ======================= classifier (consumer) blocks ===================
    const int kx = blk - N_B;                          // 0..7
    const int t  = tid & 127;                          // k-lane (0..124 active)
    const int jq = tid >> 7;                           // j-quarter (0..3)
    const int k  = kx * KCHUNK + t;
    const bool kv = (t < KCHUNK);

    __shared__ unsigned int s_tag;
    if (tid == 0) {
        unsigned long long my = atomicAdd(&g_cls_ctr, 1ULL);
        s_tag = (unsigned int)(my / NCLS_BLK) + 1u;    // overlaps loads below
    }

    // Hoist all global loads (one DRAM round, MLP=33)
    float wreg[32];
    float cbreg = 0.f;
    if (kv) {
        const int jbase = jq * 32;
        #pragma unroll
        for (int jj = 0; jj < 32; jj++)
            wreg[jj] = __ldg(&cls_w[(jbase + jj) * N_CLS + k]);
        if (jq == 0) cbreg = __ldg(&cls_b[k]);
    }

    __shared__ float  sw[4][INNER];                    // [bias, ws0, ws1, ws2][j]
    __shared__ float  part[4][4][INNER];               // [jq][A/W0/W1/W2][t]
    __shared__ float4 sP[KCHUNK];                      // {A+cls_b, W0, W1, W2}

    if (tid < INNER) {
        float w0 = 0.f, w1 = 0.f, w2 = 0.f;
        #pragma unroll
        for (int l = 0; l < N_LVL; l++) {
            w0 += emb_w[(3 * l + 0) * N_EMBD + ROOT_OFF + tid];
            w1 += emb_w[(3 * l + 1) * N_EMBD + ROOT_OFF + tid];
            w2 += emb_w[(3 * l + 2) * N_EMBD + ROOT_OFF + tid];
        }
        sw[0][tid] = emb_b[ROOT_OFF + tid];
        sw[1][tid] = w0;  sw[2][tid] = w1;  sw[3][tid] = w2;
    }
    __syncthreads();

    float aA = 0.f, a0 = 0.f, a1 = 0.f, a2 = 0.f;
    if (kv) {
        const int jbase = jq * 32;
        #pragma unroll
        for (int jj = 0; jj < 32; jj++) {
            const float w = wreg[jj];
            aA = fmaf(sw[0][jbase + jj], w, aA);
            a0 = fmaf(sw[1][jbase + jj], w, a0);
            a1 = fmaf(sw[2][jbase + jj], w, a1);
            a2 = fmaf(sw[3][jbase + jj], w, a2);
        }
    }
    part[jq][0][t] = (jq == 0) ? aA + cbreg : aA;      // fold cls_b into A
    part[jq][1][t] = a0;
    part[jq][2][t] = a1;
    part[jq][3][t] = a2;
    __syncthreads();

    if (tid < KCHUNK) {
        sP[tid] = make_float4(
            part[0][0][tid] + part[1][0][tid] + part[2][0][tid] + part[3][0][tid],
            part[0][1][tid] + part[1][1][tid] + part[2][1][tid] + part[3][1][tid],
            part[0][2][tid] + part[1][2][tid] + part[2][2][tid] + part[3][2][tid],
            part[0][3][tid] + part[1][3][tid] + part[2][3][tid] + part[3][3][tid]);
    }
    __syncthreads();                                   // sP + s_tag visible

    // Per-warp tagged-line poll + immediate writes. Warp w owns batches
    // {2w, 2w+1}; flag and payload arrive in the same 16B L2 read.
    const unsigned int tag = s_tag;
    const int wax = tid >> 5;
    #pragma unroll
    for (int q = 0; q < 2; q++) {
        const int b = wax * 2 + q;
        const float* cp = (const float*)&g_coef[b];
        float cx, cy, cz, cw;
        do {
            asm volatile("ld.global.cg.v4.f32 {%0,%1,%2,%3}, [%4];"
                         : "=f"(cx), "=f"(cy), "=f"(cz), "=f"(cw)
                         : "l"(cp) : "memory");
        } while (__float_as_uint(cw) != tag);

        float* ob = out + (size_t)b * N_CLS + kx * KCHUNK;
        #pragma unroll
        for (int kk = 0; kk < 4; kk++) {
            const int kl = kk * 32 + lane;
            if (kl < KCHUNK) {
                const float4 P = sP[kl];
                ob[kl] = P.x + fmaf(cx, P.y, fmaf(cy, P.z, cz * P.w));
            }
        }
    }
}

// ---------------------------------------------------------------------------
// Launch. Inputs (metadata order): x, emb_w, emb_b, cls_w, cls_b. Output f32.
// Graph-capturable: one kernel launch, no allocs, no syncs.
// ---------------------------------------------------------------------------
extern "C" void kernel_launch(void* const* d_in, const int* in_sizes, int n_in,
                              void* d_out, int out_size)
{
    const float* x     = (const float*)d_in[0];
    const float* emb_w = (const float*)d_in[1];
    const float* emb_b = (const float*)d_in[2];
    const float* cls_w = (const float*)d_in[3];
    const float* cls_b = (const float*)d_in[4];
    float* out = (float*)d_out;

    k_all<<<NBLK, NTHR>>>(x, emb_w, emb_b, cls_w, cls_b, out);
}

// round 9
// speedup vs baseline: 1.0407x; 1.0407x over previous
#include <cuda_runtime.h>
#include <cuda_bf16.h>

// Problem constants (fixed by reference setup_inputs)
#define N_B      32
#define N_C      3
#define HW       4096      // 64*64
#define HW4      1024      // HW / 4
#define N_EMBD   896
#define INNER    128       // 896 / 7
#define N_LVL    7
#define N_CLS    1000
#define ROOT_OFF 768       // 6 * INNER

#define NBLK     40        // 32 mean blocks + 8 classifier blocks
#define NTHR     512
#define KCHUNK   128       // k per classifier block (8*128=1024, guard k<1000)
#define NCLS_BLK 8

// Scratch (__device__ globals; allocations forbidden). Counters are monotonic
// (never reset) => generation = count/N is the launch index, valid on the
// correctness call and every graph replay (launches are stream-ordered).
__device__ float4 g_coef[N_B];              // {c0, c1, c2, tag_bits}
__device__ unsigned long long g_mean_ctr;   // +32 per launch (gen source only)
__device__ unsigned long long g_cls_ctr;    // +8  per launch (gen source only)

// ---------------------------------------------------------------------------
// One kernel. Tagged-data sync (flag rides in the 16B coef line).
//  blocks 0..31  (mean): gen atomic (overlaps x loads), channel means,
//                        ONE stcg of {c0,c1,c2,gen+1}, EXIT.
//  blocks 32..39 (cls):  gen atomic, hoisted cls_w/cls_b loads (full-warp,
//                        128-wide k), emb_w collapse -> sP in shared; each
//                        WARP polls BOTH of its batches' tagged lines at once,
//                        then emits one STG.128 per lane per batch.
// ---------------------------------------------------------------------------
__global__ __launch_bounds__(NTHR) void k_all(
    const float* __restrict__ x,
    const float* __restrict__ emb_w,
    const float* __restrict__ emb_b,
    const float* __restrict__ cls_w,
    const float* __restrict__ cls_b,
    float* __restrict__ out)
{
    const int tid  = threadIdx.x;
    const int blk  = blockIdx.x;
    const int lane = tid & 31;

    if (blk < N_B) {
        // ======================= mean (publisher) blocks ====================
        unsigned int tag = 0;
        if (tid == 0) {
            unsigned long long my = atomicAdd(&g_mean_ctr, 1ULL);
            tag = (unsigned int)(my / N_B) + 1u;       // overlaps x loads
        }
        const float4* xb = (const float4*)(x + (size_t)blk * (N_C * HW));
        float s0, s1, s2;
        {
            float4 a0 = xb[0 * HW4 + tid], a1 = xb[0 * HW4 + 512 + tid];
            float4 b0 = xb[1 * HW4 + tid], b1 = xb[1 * HW4 + 512 + tid];
            float4 c0 = xb[2 * HW4 + tid], c1 = xb[2 * HW4 + 512 + tid];
            s0 = (a0.x + a0.y + a0.z + a0.w) + (a1.x + a1.y + a1.z + a1.w);
            s1 = (b0.x + b0.y + b0.z + b0.w) + (b1.x + b1.y + b1.z + b1.w);
            s2 = (c0.x + c0.y + c0.z + c0.w) + (c1.x + c1.y + c1.z + c1.w);
        }
        #pragma unroll
        for (int off = 16; off > 0; off >>= 1) {
            s0 += __shfl_xor_sync(0xFFFFFFFFu, s0, off);
            s1 += __shfl_xor_sync(0xFFFFFFFFu, s1, off);
            s2 += __shfl_xor_sync(0xFFFFFFFFu, s2, off);
        }
        __shared__ float wr[16][3];
        const int wid = tid >> 5;
        if (lane == 0) { wr[wid][0] = s0; wr[wid][1] = s1; wr[wid][2] = s2; }
        __syncthreads();
        if (tid < 16) {
            float a0 = wr[tid][0], a1 = wr[tid][1], a2 = wr[tid][2];
            #pragma unroll
            for (int off = 8; off > 0; off >>= 1) {
                a0 += __shfl_xor_sync(0xFFFFu, a0, off);
                a1 += __shfl_xor_sync(0xFFFFu, a1, off);
                a2 += __shfl_xor_sync(0xFFFFu, a2, off);
            }
            if (tid == 0) {
                float4 cf = make_float4(a0 * (1.0f / HW), a1 * (1.0f / HW),
                                        a2 * (1.0f / HW), __uint_as_float(tag));
                __stcg(&g_coef[blk], cf);              // data + tag, one sector
            }
        }
        return;                                        // publishers exit
    }

    // ======================= classifier (consumer) blocks ===================
    const int kx = blk - N_B;                          // 0..7
    const int t  = tid & 127;                          // k-lane (0..127)
    const int jq = tid >> 7;                           // j-quarter (0..3)
    const int k  = kx * KCHUNK + t;
    const bool kv = (k < N_CLS);

    __shared__ unsigned int s_tag;
    if (tid == 0) {
        unsigned long long my = atomicAdd(&g_cls_ctr, 1ULL);
        s_tag = (unsigned int)(my / NCLS_BLK) + 1u;    // overlaps loads below
    }

    // Hoist all global loads (one DRAM/L2 round, MLP=33)
    float wreg[32];
    float cbreg = 0.f;
    {
        const int jbase = jq * 32;
        #pragma unroll
        for (int jj = 0; jj < 32; jj++)
            wreg[jj] = kv ? __ldg(&cls_w[(jbase + jj) * N_CLS + k]) : 0.f;
        if (jq == 0 && kv) cbreg = __ldg(&cls_b[k]);
    }

    __shared__ float  sw[4][INNER];                    // [bias, ws0, ws1, ws2][j]
    __shared__ float  part[4][4][KCHUNK];              // [jq][A/W0/W1/W2][t]
    __shared__ float4 sP[KCHUNK];                      // {A+cls_b, W0, W1, W2}

    if (tid < INNER) {
        float w0 = 0.f, w1 = 0.f, w2 = 0.f;
        #pragma unroll
        for (int l = 0; l < N_LVL; l++) {
            w0 += emb_w[(3 * l + 0) * N_EMBD + ROOT_OFF + tid];
            w1 += emb_w[(3 * l + 1) * N_EMBD + ROOT_OFF + tid];
            w2 += emb_w[(3 * l + 2) * N_EMBD + ROOT_OFF + tid];
        }
        sw[0][tid] = emb_b[ROOT_OFF + tid];
        sw[1][tid] = w0;  sw[2][tid] = w1;  sw[3][tid] = w2;
    }
    __syncthreads();

    float aA = 0.f, a0 = 0.f, a1 = 0.f, a2 = 0.f;
    {
        const int jbase = jq * 32;
        #pragma unroll
        for (int jj = 0; jj < 32; jj++) {
            const float w = wreg[jj];
            aA = fmaf(sw[0][jbase + jj], w, aA);
            a0 = fmaf(sw[1][jbase + jj], w, a0);
            a1 = fmaf(sw[2][jbase + jj], w, a1);
            a2 = fmaf(sw[3][jbase + jj], w, a2);
        }
    }
    part[jq][0][t] = (jq == 0) ? aA + cbreg : aA;      // fold cls_b into A
    part[jq][1][t] = a0;
    part[jq][2][t] = a1;
    part[jq][3][t] = a2;
    __syncthreads();

    if (tid < KCHUNK) {
        sP[tid] = make_float4(
            part[0][0][tid] + part[1][0][tid] + part[2][0][tid] + part[3][0][tid],
            part[0][1][tid] + part[1][1][tid] + part[2][1][tid] + part[3][1][tid],
            part[0][2][tid] + part[1][2][tid] + part[2][2][tid] + part[3][2][tid],
            part[0][3][tid] + part[1][3][tid] + part[2][3][tid] + part[3][3][tid]);
    }
    __syncthreads();                                   // sP + s_tag visible

    // Per-warp: poll BOTH owned batches' tagged lines concurrently, then store.
    const unsigned int tag = s_tag;
    const int wax = tid >> 5;                          // warp -> batches {2w,2w+1}
    const float* cp0 = (const float*)&g_coef[wax * 2 + 0];
    const float* cp1 = (const float*)&g_coef[wax * 2 + 1];
    float c0x, c0y, c0z, c0w, c1x, c1y, c1z, c1w;
    do {
        asm volatile("ld.global.cg.v4.f32 {%0,%1,%2,%3}, [%4];"
                     : "=f"(c0x), "=f"(c0y), "=f"(c0z), "=f"(c0w)
                     : "l"(cp0) : "memory");
        asm volatile("ld.global.cg.v4.f32 {%0,%1,%2,%3}, [%4];"
                     : "=f"(c1x), "=f"(c1y), "=f"(c1z), "=f"(c1w)
                     : "l"(cp1) : "memory");
    } while (__float_as_uint(c0w) != tag || __float_as_uint(c1w) != tag);

    // One STG.128 per lane per batch: lane covers k-quad kx*128 + lane*4.
    const int kbase = kx * KCHUNK + lane * 4;
    if (kbase < N_CLS) {                               // 1000 % 4 == 0 => all-or-none
        const float4 P0 = sP[lane * 4 + 0];
        const float4 P1 = sP[lane * 4 + 1];
        const float4 P2 = sP[lane * 4 + 2];
        const float4 P3 = sP[lane * 4 + 3];
        {
            const int b = wax * 2 + 0;
            float4 o;
            o.x = P0.x + fmaf(c0x, P0.y, fmaf(c0y, P0.z, c0z * P0.w));
            o.y = P1.x + fmaf(c0x, P1.y, fmaf(c0y, P1.z, c0z * P1.w));
            o.z = P2.x + fmaf(c0x, P2.y, fmaf(c0y, P2.z, c0z * P2.w));
            o.w = P3.x + fmaf(c0x, P3.y, fmaf(c0y, P3.z, c0z * P3.w));
            *(float4*)(out + (size_t)b * N_CLS + kbase) = o;
        }
        {
            const int b = wax * 2 + 1;
            float4 o;
            o.x = P0.x + fmaf(c1x, P0.y, fmaf(c1y, P0.z, c1z * P0.w));
            o.y = P1.x + fmaf(c1x, P1.y, fmaf(c1y, P1.z, c1z * P1.w));
            o.z = P2.x + fmaf(c1x, P2.y, fmaf(c1y, P2.z, c1z * P2.w));
            o.w = P3.x + fmaf(c1x, P3.y, fmaf(c1y, P3.z, c1z * P3.w));
            *(float4*)(out + (size_t)b * N_CLS + kbase) = o;
        }
    }
}

// ---------------------------------------------------------------------------
// Launch. Inputs (metadata order): x, emb_w, emb_b, cls_w, cls_b. Output f32.
// Graph-capturable: one kernel launch, no allocs, no syncs.
// ---------------------------------------------------------------------------
extern "C" void kernel_launch(void* const* d_in, const int* in_sizes, int n_in,
                              void* d_out, int out_size)
{
    const float* x     = (const float*)d_in[0];
    const float* emb_w = (const float*)d_in[1];
    const float* emb_b = (const float*)d_in[2];
    const float* cls_w = (const float*)d_in[3];
    const float* cls_b = (const float*)d_in[4];
    float* out = (float*)d_out;

    k_all<<<NBLK, NTHR>>>(x, emb_w, emb_b, cls_w, cls_b, out);
}

// round 12
// speedup vs baseline: 1.3381x; 1.2857x over previous
#include <cuda_runtime.h>
#include <cuda_bf16.h>

// Problem constants (fixed by reference setup_inputs)
#define N_B      32
#define N_C      3
#define HW       4096      // 64*64
#define HW4      1024      // float4 per channel
#define N_EMBD   896
#define INNER    128
#define N_LVL    7
#define N_CLS    1000
#define ROOT_OFF 768       // 6 * INNER

#define NMEAN    64        // 2 half-blocks per batch
#define NCLSB    16        // 16 classifier blocks, 64 k each
#define NBLK     (NMEAN + NCLSB)   // 80 (one wave)
#define NTHR     512
#define KCH      64        // k per classifier block

// Scratch (__device__ globals; allocations forbidden). Counters monotonic =>
// generation = count/N is the launch index; valid on correctness call and
// every graph replay (stream-ordered launches).
__device__ float4 g_half[NMEAN];            // {s0, s1, s2, tag_bits} raw half-sums
__device__ unsigned long long g_mean_ctr;   // +64 per launch
__device__ unsigned long long g_cls_ctr;    // +16 per launch

// ---------------------------------------------------------------------------
// One kernel, tagged-data sync, halved per-block L1 load floors:
//  blocks 0..63  : batch b=blk>>1, half h=blk&1 — 24KB x slice, raw channel
//                  sums published as ONE tagged 16B stcg. EXIT.
//  blocks 64..79 : 64-k chunk — 32KB cls_w hoisted, emb_w collapse,
//                  sP={A+cls_b,W0,W1,W2}; per-warp poll of 4 half-lines
//                  (2 batches x 2 halves), combine halves, float2 stores.
// ---------------------------------------------------------------------------
__global__ __launch_bounds__(NTHR) void k_all(
    const float* __restrict__ x,
    const float* __restrict__ emb_w,
    const float* __restrict__ emb_b,
    const float* __restrict__ cls_w,
    const float* __restrict__ cls_b,
    float* __restrict__ out)
{
    const int tid  = threadIdx.x;
    const int blk  = blockIdx.x;
    const int lane = tid & 31;

    if (blk < NMEAN) {
        // ======================= mean half-blocks (publishers) ==============
        unsigned int tag = 0;
        if (tid == 0) {
            unsigned long long my = atomicAdd(&g_mean_ctr, 1ULL);
            tag = (unsigned int)(my / NMEAN) + 1u;     // overlaps x loads
        }
        const int b = blk >> 1, h = blk & 1;
        const float4* xb = (const float4*)(x + (size_t)b * (N_C * HW));
        const int off = h * 512 + tid;                 // half of each channel
        float s0, s1, s2;
        {
            float4 a = xb[0 * HW4 + off];
            float4 c = xb[1 * HW4 + off];
            float4 d = xb[2 * HW4 + off];
            s0 = (a.x + a.y) + (a.z + a.w);
            s1 = (c.x + c.y) + (c.z + c.w);
            s2 = (d.x + d.y) + (d.z + d.w);
        }
        #pragma unroll
        for (int o = 16; o > 0; o >>= 1) {
            s0 += __shfl_xor_sync(0xFFFFFFFFu, s0, o);
            s1 += __shfl_xor_sync(0xFFFFFFFFu, s1, o);
            s2 += __shfl_xor_sync(0xFFFFFFFFu, s2, o);
        }
        __shared__ float wr[16][3];
        const int wid = tid >> 5;
        if (lane == 0) { wr[wid][0] = s0; wr[wid][1] = s1; wr[wid][2] = s2; }
        __syncthreads();
        if (tid < 16) {
            float a0 = wr[tid][0], a1 = wr[tid][1], a2 = wr[tid][2];
            #pragma unroll
            for (int o = 8; o > 0; o >>= 1) {
                a0 += __shfl_xor_sync(0xFFFFu, a0, o);
                a1 += __shfl_xor_sync(0xFFFFu, a1, o);
                a2 += __shfl_xor_sync(0xFFFFu, a2, o);
            }
            if (tid == 0) {
                // raw half-sums + tag, one 16B sector
                float4 cf = make_float4(a0, a1, a2, __uint_as_float(tag));
                __stcg(&g_half[blk], cf);
            }
        }
        return;
    }

    // ======================= classifier (consumer) blocks ===================
    const int kq = blk - NMEAN;                        // 0..15
    const int t  = tid & 63;                           // k-lane (0..63)
    const int jg = tid >> 6;                           // j-group (0..7), 16 j each
    const int k  = kq * KCH + t;
    const int keff = (k < N_CLS) ? k : (N_CLS - 1);    // clamp OOB reads

    __shared__ unsigned int s_tag;
    if (tid == 0) {
        unsigned long long my = atomicAdd(&g_cls_ctr, 1ULL);
        s_tag = (unsigned int)(my / NCLSB) + 1u;       // overlaps loads below
    }

    // Hoist cls_w loads (16/thread, warp-coalesced: 32 consecutive keff)
    float wreg[16];
    float cbreg = 0.f;
    {
        const int jbase = jg * 16;
        #pragma unroll
        for (int jj = 0; jj < 16; jj++)
            wreg[jj] = __ldg(&cls_w[(jbase + jj) * N_CLS + keff]);
        if (jg == 0) cbreg = __ldg(&cls_b[keff]);
    }

    __shared__ float  sw[4][INNER];                    // [bias, ws0, ws1, ws2][j]
    __shared__ float  part[8][4][KCH];                 // [jg][A/W0/W1/W2][t]
    __shared__ float4 sP[KCH];                         // {A+cls_b, W0, W1, W2}

    if (tid < INNER) {
        float w0 = 0.f, w1 = 0.f, w2 = 0.f;
        #pragma unroll
        for (int l = 0; l < N_LVL; l++) {
            w0 += emb_w[(3 * l + 0) * N_EMBD + ROOT_OFF + tid];
            w1 += emb_w[(3 * l + 1) * N_EMBD + ROOT_OFF + tid];
            w2 += emb_w[(3 * l + 2) * N_EMBD + ROOT_OFF + tid];
        }
        sw[0][tid] = emb_b[ROOT_OFF + tid];
        sw[1][tid] = w0;  sw[2][tid] = w1;  sw[3][tid] = w2;
    }
    __syncthreads();

    float aA = 0.f, a0 = 0.f, a1 = 0.f, a2 = 0.f;
    {
        const int jbase = jg * 16;
        #pragma unroll
        for (int jj = 0; jj < 16; jj++) {
            const float w = wreg[jj];
            aA = fmaf(sw[0][jbase + jj], w, aA);
            a0 = fmaf(sw[1][jbase + jj], w, a0);
            a1 = fmaf(sw[2][jbase + jj], w, a1);
            a2 = fmaf(sw[3][jbase + jj], w, a2);
        }
    }
    part[jg][0][t] = (jg == 0) ? aA + cbreg : aA;      // fold cls_b into A
    part[jg][1][t] = a0;
    part[jg][2][t] = a1;
    part[jg][3][t] = a2;
    __syncthreads();

    if (tid < KCH) {
        float A = 0.f, W0 = 0.f, W1 = 0.f, W2 = 0.f;
        #pragma unroll
        for (int g = 0; g < 8; g++) {
            A  += part[g][0][tid];
            W0 += part[g][1][tid];
            W1 += part[g][2][tid];
            W2 += part[g][3][tid];
        }
        sP[tid] = make_float4(A, W0, W1, W2);
    }
    __syncthreads();                                   // sP + s_tag visible

    // Per-warp: poll the 4 half-lines of its 2 batches, combine, store.
    const unsigned int tag = s_tag;
    const int wax = tid >> 5;                          // warp -> batches {2w, 2w+1}
    const float4* hp = &g_half[wax * 4];               // halves [4w .. 4w+3]
    float h0x,h0y,h0z,h0w, h1x,h1y,h1z,h1w, h2x,h2y,h2z,h2w, h3x,h3y,h3z,h3w;
    do {
        asm volatile("ld.global.cg.v4.f32 {%0,%1,%2,%3}, [%4];"
                     : "=f"(h0x),"=f"(h0y),"=f"(h0z),"=f"(h0w)
                     : "l"(hp + 0) : "memory");
        asm volatile("ld.global.cg.v4.f32 {%0,%1,%2,%3}, [%4];"
                     : "=f"(h1x),"=f"(h1y),"=f"(h1z),"=f"(h1w)
                     : "l"(hp + 1) : "memory");
        asm volatile("ld.global.cg.v4.f32 {%0,%1,%2,%3}, [%4];"
                     : "=f"(h2x),"=f"(h2y),"=f"(h2z),"=f"(h2w)
                     : "l"(hp + 2) : "memory");
        asm volatile("ld.global.cg.v4.f32 {%0,%1,%2,%3}, [%4];"
                     : "=f"(h3x),"=f"(h3y),"=f"(h3z),"=f"(h3w)
                     : "l"(hp + 3) : "memory");
    } while (__float_as_uint(h0w) != tag || __float_as_uint(h1w) != tag ||
             __float_as_uint(h2w) != tag || __float_as_uint(h3w) != tag);

    const int kbase = kq * KCH + lane * 2;
    if (kbase < N_CLS) {                               // 1000 even => no straddle
        const float4 P0 = sP[lane * 2 + 0];
        const float4 P1 = sP[lane * 2 + 1];
        const float inv = 1.0f / HW;
        {   // batch 2*wax  (halves 0,1)
            const float c0 = (h0x + h1x) * inv;
            const float c1 = (h0y + h1y) * inv;
            const float c2 = (h0z + h1z) * inv;
            float2 o;
            o.x = P0.x + fmaf(c0, P0.y, fmaf(c1, P0.z, c2 * P0.w));
            o.y = P1.x + fmaf(c0, P1.y, fmaf(c1, P1.z, c2 * P1.w));
            *(float2*)(out + (size_t)(wax * 2 + 0) * N_CLS + kbase) = o;
        }
        {   // batch 2*wax+1 (halves 2,3)
            const float c0 = (h2x + h3x) * inv;
            const float c1 = (h2y + h3y) * inv;
            const float c2 = (h2z + h3z) * inv;
            float2 o;
            o.x = P0.x + fmaf(c0, P0.y, fmaf(c1, P0.z, c2 * P0.w));
            o.y = P1.x + fmaf(c0, P1.y, fmaf(c1, P1.z, c2 * P1.w));
            *(float2*)(out + (size_t)(wax * 2 + 1) * N_CLS + kbase) = o;
        }
    }
}

// ---------------------------------------------------------------------------
// Launch. Inputs (metadata order): x, emb_w, emb_b, cls_w, cls_b. Output f32.
// Graph-capturable: one kernel launch, no allocs, no syncs.
// ---------------------------------------------------------------------------
extern "C" void kernel_launch(void* const* d_in, const int* in_sizes, int n_in,
                              void* d_out, int out_size)
{
    const float* x     = (const float*)d_in[0];
    const float* emb_w = (const float*)d_in[1];
    const float* emb_b = (const float*)d_in[2];
    const float* cls_w = (const float*)d_in[3];
    const float* cls_b = (const float*)d_in[4];
    float* out = (float*)d_out;

    k_all<<<NBLK, NTHR>>>(x, emb_w, emb_b, cls_w, cls_b, out);
}